// round 10
// baseline (speedup 1.0000x reference)
#include <cuda_runtime.h>
#include <cstdint>

#define B 8
#define S 2048
#define DM 1024
#define DK 64
#define ROWS (B * S)

// ---------------- scratch (device globals; no allocation allowed) ----------
__device__ float g_Q[ROWS * DK];            // 4 MB
__device__ float g_K[ROWS * DK];            // 4 MB
__device__ float g_V[ROWS * DM];            // 64 MB
__device__ float g_L[ROWS];
__device__ float g_P[(size_t)ROWS * S];     // 134 MB score / prob matrix
__device__ float g_WvT[DM * DM];            // Wv^T, K-major, tf32-rounded
__device__ float g_WqkT[128 * DM];          // [Wq|Wk]^T, K-major, tf32-rounded
__device__ float g_bqk[128];

// ======================= helpers ==========================================
__device__ __forceinline__ uint32_t f2tf32(float f) {
    uint32_t o;
    asm("cvt.rna.tf32.f32 %0, %1;" : "=r"(o) : "f"(f));
    return o;
}

__device__ __forceinline__ void mma_tf32(float c[4], const uint32_t a[4],
                                         const uint32_t b[2]) {
    asm volatile(
        "mma.sync.aligned.m16n8k8.row.col.f32.tf32.tf32.f32 "
        "{%0,%1,%2,%3}, {%4,%5,%6,%7}, {%8,%9}, {%0,%1,%2,%3};"
        : "+f"(c[0]), "+f"(c[1]), "+f"(c[2]), "+f"(c[3])
        : "r"(a[0]), "r"(a[1]), "r"(a[2]), "r"(a[3]), "r"(b[0]), "r"(b[1]));
}

// ===========================================================================
// Prep: tiled transposes into K-major weight copies (values tf32-rounded)
// ===========================================================================
__global__ __launch_bounds__(256) void transpose_wv_kernel(const float* __restrict__ Wv)
{
    __shared__ float t[32][33];
    const int k0 = blockIdx.x * 32, n0 = blockIdx.y * 32;
    const int tx = threadIdx.x, ty = threadIdx.y;
#pragma unroll
    for (int i = 0; i < 32; i += 8)
        t[ty + i][tx] = Wv[(k0 + ty + i) * DM + n0 + tx];
    __syncthreads();
#pragma unroll
    for (int i = 0; i < 32; i += 8)
        g_WvT[(n0 + ty + i) * DM + k0 + tx] =
            __uint_as_float(f2tf32(t[tx][ty + i]));
}

__global__ __launch_bounds__(256) void prep_qk_kernel(
    const float* __restrict__ Wq, const float* __restrict__ bq,
    const float* __restrict__ Wk, const float* __restrict__ bk)
{
    __shared__ float t[32][33];
    const int k0 = blockIdx.x * 32, n0 = blockIdx.y * 32;
    const int tx = threadIdx.x, ty = threadIdx.y;
    const int n = n0 + tx;
#pragma unroll
    for (int i = 0; i < 32; i += 8) {
        int k = k0 + ty + i;
        t[ty + i][tx] = (n < 64) ? Wq[k * DK + n] : Wk[k * DK + (n - 64)];
    }
    __syncthreads();
#pragma unroll
    for (int i = 0; i < 32; i += 8)
        g_WqkT[(n0 + ty + i) * DM + k0 + tx] =
            __uint_as_float(f2tf32(t[tx][ty + i]));
    if (blockIdx.x == 0 && blockIdx.y == 0) {
        int id = ty * 32 + tx;
        if (id < 128) g_bqk[id] = (id < 64) ? bq[id] : bk[id - 64];
    }
}

// ===========================================================================
// tf32 mma.sync GEMM (projections), double-buffered smem + reg prefetch.
// mode 0: g_V (+bv), mode 1: g_Q|g_K.
// BM=128 BN=128 BK=16, 256 thr (8 warps, 2x4), warp tile 64x32 (m16n8k8).
// ===========================================================================
#define PAD 20
__global__ __launch_bounds__(256, 2) void gemm_tc_kernel(
    const float* __restrict__ A, const float* __restrict__ bv, int mode)
{
    __shared__ uint32_t sA[2][128 * PAD];
    __shared__ uint32_t sB[2][128 * PAD];

    const float* Bt = mode ? g_WqkT : g_WvT;

    const int r0   = blockIdx.x * 128;
    const int nc   = blockIdx.y * 128;
    const int tid  = threadIdx.x;
    const int wid  = tid >> 5;
    const int lane = tid & 31;
    const int wm   = (wid >> 2) * 64;
    const int wn   = (wid & 3) * 32;
    const int lr   = lane >> 2;
    const int lc   = lane & 3;

    float acc[4][4][4];
#pragma unroll
    for (int mi = 0; mi < 4; mi++)
#pragma unroll
        for (int ni = 0; ni < 4; ni++)
#pragma unroll
            for (int r = 0; r < 4; r++) acc[mi][ni][r] = 0.f;

    float4 pa[2], pb[2];
#pragma unroll
    for (int it = 0; it < 2; it++) {
        int lin = tid + it * 256;
        int m = lin >> 2, k4 = lin & 3;
        pa[it] = *reinterpret_cast<const float4*>(&A[(size_t)(r0 + m) * DM + k4 * 4]);
        pb[it] = *reinterpret_cast<const float4*>(&Bt[(size_t)(nc + m) * DM + k4 * 4]);
    }
#pragma unroll
    for (int it = 0; it < 2; it++) {
        int lin = tid + it * 256;
        int m = lin >> 2, k4 = lin & 3;
        uint32_t* da = &sA[0][m * PAD + k4 * 4];
        da[0] = f2tf32(pa[it].x); da[1] = f2tf32(pa[it].y);
        da[2] = f2tf32(pa[it].z); da[3] = f2tf32(pa[it].w);
        uint32_t* db = &sB[0][m * PAD + k4 * 4];
        db[0] = __float_as_uint(pb[it].x); db[1] = __float_as_uint(pb[it].y);
        db[2] = __float_as_uint(pb[it].z); db[3] = __float_as_uint(pb[it].w);
    }
    __syncthreads();

    int cur = 0;
    const int NT = DM / 16;
    for (int kt = 0; kt < NT; kt++) {
        if (kt + 1 < NT) {
            const int kc = (kt + 1) * 16;
#pragma unroll
            for (int it = 0; it < 2; it++) {
                int lin = tid + it * 256;
                int m = lin >> 2, k4 = lin & 3;
                pa[it] = *reinterpret_cast<const float4*>(
                    &A[(size_t)(r0 + m) * DM + kc + k4 * 4]);
                pb[it] = *reinterpret_cast<const float4*>(
                    &Bt[(size_t)(nc + m) * DM + kc + k4 * 4]);
            }
        }
        const uint32_t* cA = sA[cur];
        const uint32_t* cB = sB[cur];
#pragma unroll
        for (int ks = 0; ks < 2; ks++) {
            const int k0 = ks * 8;
            uint32_t a[4][4], b[4][2];
#pragma unroll
            for (int mi = 0; mi < 4; mi++) {
                const uint32_t* p = &cA[(wm + mi * 16 + lr) * PAD + k0 + lc];
                a[mi][0] = p[0];
                a[mi][1] = p[8 * PAD];
                a[mi][2] = p[4];
                a[mi][3] = p[8 * PAD + 4];
            }
#pragma unroll
            for (int ni = 0; ni < 4; ni++) {
                const uint32_t* p = &cB[(wn + ni * 8 + lr) * PAD + k0 + lc];
                b[ni][0] = p[0];
                b[ni][1] = p[4];
            }
#pragma unroll
            for (int mi = 0; mi < 4; mi++)
#pragma unroll
                for (int ni = 0; ni < 4; ni++)
                    mma_tf32(acc[mi][ni], a[mi], b[ni]);
        }
        if (kt + 1 < NT) {
            uint32_t* nA = sA[cur ^ 1];
            uint32_t* nB = sB[cur ^ 1];
#pragma unroll
            for (int it = 0; it < 2; it++) {
                int lin = tid + it * 256;
                int m = lin >> 2, k4 = lin & 3;
                uint32_t* da = &nA[m * PAD + k4 * 4];
                da[0] = f2tf32(pa[it].x); da[1] = f2tf32(pa[it].y);
                da[2] = f2tf32(pa[it].z); da[3] = f2tf32(pa[it].w);
                uint32_t* db = &nB[m * PAD + k4 * 4];
                db[0] = __float_as_uint(pb[it].x); db[1] = __float_as_uint(pb[it].y);
                db[2] = __float_as_uint(pb[it].z); db[3] = __float_as_uint(pb[it].w);
            }
        }
        __syncthreads();
        cur ^= 1;
    }

#pragma unroll
    for (int mi = 0; mi < 4; mi++) {
#pragma unroll
        for (int ni = 0; ni < 4; ni++) {
#pragma unroll
            for (int h = 0; h < 2; h++) {
                int row = r0 + wm + mi * 16 + lr + h * 8;
                int col = wn + ni * 8 + 2 * lc;
                float v0 = acc[mi][ni][h * 2 + 0];
                float v1 = acc[mi][ni][h * 2 + 1];
                if (mode == 0) {
                    float2 o = {v0 + bv[nc + col], v1 + bv[nc + col + 1]};
                    *reinterpret_cast<float2*>(
                        &g_V[(size_t)row * DM + nc + col]) = o;
                } else {
                    float w0 = v0 + g_bqk[col];
                    float w1 = v1 + g_bqk[col + 1];
                    float2 o = {w0, w1};
                    if (col < 64)
                        *reinterpret_cast<float2*>(&g_Q[(size_t)row * DK + col]) = o;
                    else
                        *reinterpret_cast<float2*>(
                            &g_K[(size_t)row * DK + (col - 64)]) = o;
                }
            }
        }
    }
}

// ===========================================================================
// score_kernel: one 128x128 causal tile of S = Q K^T / 8 per CTA.
// Double-buffered, 4 k-iterations (DK=64, BK=16).
// ===========================================================================
__global__ __launch_bounds__(256, 2) void score_kernel()
{
    __shared__ uint32_t sA[2][128 * PAD];
    __shared__ uint32_t sB[2][128 * PAD];

    int i = blockIdx.x;
    int qt = (int)((sqrtf(8.f * (float)i + 1.f) - 1.f) * 0.5f);
    while ((qt + 1) * (qt + 2) / 2 <= i) qt++;
    while (qt * (qt + 1) / 2 > i) qt--;
    const int kt = i - qt * (qt + 1) / 2;

    const int b     = blockIdx.y;
    const int qbase = b * S + qt * 128;
    const int kbase = b * S + kt * 128;

    const int tid  = threadIdx.x;
    const int wid  = tid >> 5;
    const int lane = tid & 31;
    const int wm   = (wid >> 2) * 64;
    const int wn   = (wid & 3) * 32;
    const int lr   = lane >> 2;
    const int lc   = lane & 3;

    float acc[4][4][4];
#pragma unroll
    for (int mi = 0; mi < 4; mi++)
#pragma unroll
        for (int ni = 0; ni < 4; ni++)
#pragma unroll
            for (int r = 0; r < 4; r++) acc[mi][ni][r] = 0.f;

    float4 pa[2], pb[2];
#pragma unroll
    for (int it = 0; it < 2; it++) {
        int lin = tid + it * 256;
        int m = lin >> 2, k4 = lin & 3;
        pa[it] = *reinterpret_cast<const float4*>(&g_Q[(size_t)(qbase + m) * DK + k4 * 4]);
        pb[it] = *reinterpret_cast<const float4*>(&g_K[(size_t)(kbase + m) * DK + k4 * 4]);
    }
#pragma unroll
    for (int it = 0; it < 2; it++) {
        int lin = tid + it * 256;
        int m = lin >> 2, k4 = lin & 3;
        uint32_t* da = &sA[0][m * PAD + k4 * 4];
        da[0] = f2tf32(pa[it].x); da[1] = f2tf32(pa[it].y);
        da[2] = f2tf32(pa[it].z); da[3] = f2tf32(pa[it].w);
        uint32_t* db = &sB[0][m * PAD + k4 * 4];
        db[0] = f2tf32(pb[it].x); db[1] = f2tf32(pb[it].y);
        db[2] = f2tf32(pb[it].z); db[3] = f2tf32(pb[it].w);
    }
    __syncthreads();

    int cur = 0;
    const int NT = DK / 16;   // 4
    for (int ktile = 0; ktile < NT; ktile++) {
        if (ktile + 1 < NT) {
            const int kc = (ktile + 1) * 16;
#pragma unroll
            for (int it = 0; it < 2; it++) {
                int lin = tid + it * 256;
                int m = lin >> 2, k4 = lin & 3;
                pa[it] = *reinterpret_cast<const float4*>(
                    &g_Q[(size_t)(qbase + m) * DK + kc + k4 * 4]);
                pb[it] = *reinterpret_cast<const float4*>(
                    &g_K[(size_t)(kbase + m) * DK + kc + k4 * 4]);
            }
        }
        const uint32_t* cA = sA[cur];
        const uint32_t* cB = sB[cur];
#pragma unroll
        for (int ks = 0; ks < 2; ks++) {
            const int k0 = ks * 8;
            uint32_t a[4][4], b2[4][2];
#pragma unroll
            for (int mi = 0; mi < 4; mi++) {
                const uint32_t* p = &cA[(wm + mi * 16 + lr) * PAD + k0 + lc];
                a[mi][0] = p[0];
                a[mi][1] = p[8 * PAD];
                a[mi][2] = p[4];
                a[mi][3] = p[8 * PAD + 4];
            }
#pragma unroll
            for (int ni = 0; ni < 4; ni++) {
                const uint32_t* p = &cB[(wn + ni * 8 + lr) * PAD + k0 + lc];
                b2[ni][0] = p[0];
                b2[ni][1] = p[4];
            }
#pragma unroll
            for (int mi = 0; mi < 4; mi++)
#pragma unroll
                for (int ni = 0; ni < 4; ni++)
                    mma_tf32(acc[mi][ni], a[mi], b2[ni]);
        }
        if (ktile + 1 < NT) {
            uint32_t* nA = sA[cur ^ 1];
            uint32_t* nB = sB[cur ^ 1];
#pragma unroll
            for (int it = 0; it < 2; it++) {
                int lin = tid + it * 256;
                int m = lin >> 2, k4 = lin & 3;
                uint32_t* da = &nA[m * PAD + k4 * 4];
                da[0] = f2tf32(pa[it].x); da[1] = f2tf32(pa[it].y);
                da[2] = f2tf32(pa[it].z); da[3] = f2tf32(pa[it].w);
                uint32_t* db = &nB[m * PAD + k4 * 4];
                db[0] = f2tf32(pb[it].x); db[1] = f2tf32(pb[it].y);
                db[2] = f2tf32(pb[it].z); db[3] = f2tf32(pb[it].w);
            }
        }
        __syncthreads();
        cur ^= 1;
    }

#pragma unroll
    for (int mi = 0; mi < 4; mi++) {
#pragma unroll
        for (int ni = 0; ni < 4; ni++) {
#pragma unroll
            for (int h = 0; h < 2; h++) {
                int qrow = qt * 128 + wm + mi * 16 + lr + h * 8;
                int kcol = kt * 128 + wn + ni * 8 + 2 * lc;
                float v0 = acc[mi][ni][h * 2 + 0] * 0.125f;
                float v1 = acc[mi][ni][h * 2 + 1] * 0.125f;
                if (kcol > qrow)     v0 = -1e30f;
                if (kcol + 1 > qrow) v1 = -1e30f;
                float2 o = {v0, v1};
                *reinterpret_cast<float2*>(
                    &g_P[(size_t)(b * S + qrow) * S + kcol]) = o;
            }
        }
    }
}

// ===========================================================================
// rowexp_kernel: warp per row, branch-free float4 passes over [0, kend).
// Masked entries hold -1e30 (written by score) -> exp underflows to 0, so
// no masking and no separate zero-pad loop are needed.
// ===========================================================================
__global__ __launch_bounds__(256) void rowexp_kernel()
{
    const int tid  = threadIdx.x;
    const int wid  = tid >> 5;
    const int lane = tid & 31;
    const int row  = blockIdx.x * 8 + wid;
    const int q    = row & (S - 1);
    float4* P4 = reinterpret_cast<float4*>(&g_P[(size_t)row * S]);
    const int n4 = (((q >> 7) + 1) << 7) >> 2;   // kend / 4

    float m = -1e30f;
    for (int j = lane; j < n4; j += 32) {
        float4 v = P4[j];
        m = fmaxf(m, fmaxf(fmaxf(v.x, v.y), fmaxf(v.z, v.w)));
    }
#pragma unroll
    for (int off = 16; off > 0; off >>= 1)
        m = fmaxf(m, __shfl_xor_sync(0xffffffffu, m, off));

    float l = 0.f;
    for (int j = lane; j < n4; j += 32) {
        float4 v = P4[j];
        float4 e;
        e.x = __expf(v.x - m); e.y = __expf(v.y - m);
        e.z = __expf(v.z - m); e.w = __expf(v.w - m);
        P4[j] = e;
        l += (e.x + e.y) + (e.z + e.w);
    }
#pragma unroll
    for (int off = 16; off > 0; off >>= 1)
        l += __shfl_xor_sync(0xffffffffu, l, off);

    if (lane == 0) g_L[row] = l;
}

// ===========================================================================
// pv_kernel: O[128q x 256d tile] = (P_exp/l) @ V.  Causal k-loop.
// BM=128 BN=256 BK=16, 512 thr (16 warps, 4 m-rows x 4 n-cols, warp 32x64).
// sP double-buffered (stride 20), sV single-buffered [k][d] stride 264.
// ===========================================================================
#define STV2 264
__global__ __launch_bounds__(512) void pv_kernel(float* __restrict__ out)
{
    __shared__ uint32_t sP[2][128 * PAD];     // 20.5 KB
    __shared__ uint32_t sV[16 * STV2];        // 16.9 KB

    const int qt    = blockIdx.x;
    const int dc0   = blockIdx.y * 256;
    const int b     = blockIdx.z;
    const int base  = b * S;
    const int qbase = base + qt * 128;

    const int tid  = threadIdx.x;
    const int wid  = tid >> 5;
    const int lane = tid & 31;
    const int wm   = (wid & 3) * 32;      // warp m offset (4 rows)
    const int wn   = (wid >> 2) * 64;     // warp n offset (4 cols)
    const int lr   = lane >> 2;
    const int lc   = lane & 3;

    float acc[2][8][4];
#pragma unroll
    for (int mi = 0; mi < 2; mi++)
#pragma unroll
        for (int ni = 0; ni < 8; ni++)
#pragma unroll
            for (int r = 0; r < 4; r++) acc[mi][ni][r] = 0.f;

    // ---- prologue: tile 0 ----
    float4 pp, pv4[2];
    {
        int m = tid >> 2, k4 = tid & 3;
        pp = *reinterpret_cast<const float4*>(&g_P[(size_t)(qbase + m) * S + k4 * 4]);
#pragma unroll
        for (int it = 0; it < 2; it++) {
            int lin = tid + it * 512;
            int k = lin >> 6, d4 = lin & 63;
            pv4[it] = *reinterpret_cast<const float4*>(
                &g_V[(size_t)(base + k) * DM + dc0 + d4 * 4]);
        }
    }
    {
        int m = tid >> 2, k4 = tid & 3;
        uint32_t* dp = &sP[0][m * PAD + k4 * 4];
        dp[0] = f2tf32(pp.x); dp[1] = f2tf32(pp.y);
        dp[2] = f2tf32(pp.z); dp[3] = f2tf32(pp.w);
#pragma unroll
        for (int it = 0; it < 2; it++) {
            int lin = tid + it * 512;
            int k = lin >> 6, d4 = lin & 63;
            uint32_t* dv = &sV[k * STV2 + d4 * 4];
            dv[0] = f2tf32(pv4[it].x); dv[1] = f2tf32(pv4[it].y);
            dv[2] = f2tf32(pv4[it].z); dv[3] = f2tf32(pv4[it].w);
        }
    }
    __syncthreads();

    int cur = 0;
    const int NT = (qt + 1) * 8;      // (qt+1)*128 / 16
    for (int kt = 0; kt < NT; kt++) {
        if (kt + 1 < NT) {
            const int kc = (kt + 1) * 16;
            int m = tid >> 2, k4 = tid & 3;
            pp = *reinterpret_cast<const float4*>(
                &g_P[(size_t)(qbase + m) * S + kc + k4 * 4]);
#pragma unroll
            for (int it = 0; it < 2; it++) {
                int lin = tid + it * 512;
                int k = lin >> 6, d4 = lin & 63;
                pv4[it] = *reinterpret_cast<const float4*>(
                    &g_V[(size_t)(base + kc + k) * DM + dc0 + d4 * 4]);
            }
        }
        const uint32_t* cP = sP[cur];
#pragma unroll
        for (int ks = 0; ks < 2; ks++) {
            const int k0 = ks * 8;
            uint32_t a[2][4], b2[8][2];
#pragma unroll
            for (int mi = 0; mi < 2; mi++) {
                const uint32_t* p = &cP[(wm + mi * 16 + lr) * PAD + k0 + lc];
                a[mi][0] = p[0];
                a[mi][1] = p[8 * PAD];
                a[mi][2] = p[4];
                a[mi][3] = p[8 * PAD + 4];
            }
#pragma unroll
            for (int ni = 0; ni < 8; ni++) {
                int n = wn + ni * 8 + lr;
                b2[ni][0] = sV[(k0 + lc) * STV2 + n];
                b2[ni][1] = sV[(k0 + lc + 4) * STV2 + n];
            }
#pragma unroll
            for (int mi = 0; mi < 2; mi++)
#pragma unroll
                for (int ni = 0; ni < 8; ni++)
                    mma_tf32(acc[mi][ni], a[mi], b2[ni]);
        }
        __syncthreads();   // everyone done reading sV (and old sP)
        if (kt + 1 < NT) {
            uint32_t* nP = sP[cur ^ 1];
            int m = tid >> 2, k4 = tid & 3;
            uint32_t* dp = &nP[m * PAD + k4 * 4];
            dp[0] = f2tf32(pp.x); dp[1] = f2tf32(pp.y);
            dp[2] = f2tf32(pp.z); dp[3] = f2tf32(pp.w);
#pragma unroll
            for (int it = 0; it < 2; it++) {
                int lin = tid + it * 512;
                int k = lin >> 6, d4 = lin & 63;
                uint32_t* dv = &sV[k * STV2 + d4 * 4];
                dv[0] = f2tf32(pv4[it].x); dv[1] = f2tf32(pv4[it].y);
                dv[2] = f2tf32(pv4[it].z); dv[3] = f2tf32(pv4[it].w);
            }
        }
        __syncthreads();   // new sV / sP ready
        cur ^= 1;
    }

    // ---- epilogue: scale by 1/l, write out -------------------------------
#pragma unroll
    for (int mi = 0; mi < 2; mi++) {
#pragma unroll
        for (int h = 0; h < 2; h++) {
            int qrow = qt * 128 + wm + mi * 16 + lr + h * 8;
            float linv = 1.0f / g_L[base + qrow];
#pragma unroll
            for (int ni = 0; ni < 8; ni++) {
                int col = dc0 + wn + ni * 8 + 2 * lc;
                float2 o = {acc[mi][ni][h * 2 + 0] * linv,
                            acc[mi][ni][h * 2 + 1] * linv};
                *reinterpret_cast<float2*>(
                    &out[(size_t)(base + qrow) * DM + col]) = o;
            }
        }
    }
}

// ===========================================================================
extern "C" void kernel_launch(void* const* d_in, const int* in_sizes, int n_in,
                              void* d_out, int out_size)
{
    const float* X  = (const float*)d_in[0];
    const float* Wq = (const float*)d_in[1];
    const float* bq = (const float*)d_in[2];
    const float* Wk = (const float*)d_in[3];
    const float* bk = (const float*)d_in[4];
    const float* Wv = (const float*)d_in[5];
    const float* bv = (const float*)d_in[6];
    float* out = (float*)d_out;

    transpose_wv_kernel<<<dim3(32, 32), dim3(32, 8)>>>(Wv);
    prep_qk_kernel<<<dim3(32, 4), dim3(32, 8)>>>(Wq, bq, Wk, bk);
    gemm_tc_kernel<<<dim3(128, 1), 256>>>(X, nullptr, 1);   // Q|K projection
    gemm_tc_kernel<<<dim3(128, 8), 256>>>(X, bv, 0);        // V projection
    score_kernel<<<dim3(136, 8), 256>>>();                  // S = QK^T/8 (causal)
    rowexp_kernel<<<ROWS / 8, 256>>>();                     // softmax (in place)
    pv_kernel<<<dim3(S / 128, DM / 256, B), 512>>>(out);    // O = P V / l
}

// round 11
// speedup vs baseline: 1.2668x; 1.2668x over previous
#include <cuda_runtime.h>
#include <cstdint>

#define B 8
#define S 2048
#define DM 1024
#define DK 64
#define ROWS (B * S)

// ---------------- scratch (device globals; no allocation allowed) ----------
__device__ float g_Xt[(size_t)ROWS * DM];   // X, tf32-rounded (64 MB)
__device__ float g_Q[ROWS * DK];            // tf32-rounded
__device__ float g_K[ROWS * DK];            // tf32-rounded
__device__ float g_V[ROWS * DM];            // tf32-rounded (64 MB)
__device__ float g_L[ROWS];
__device__ float g_P[(size_t)ROWS * S];     // scores, then tf32-rounded probs
__device__ float g_WvT[DM * DM];            // Wv^T, K-major, tf32-rounded
__device__ float g_WqkT[128 * DM];          // [Wq|Wk]^T, K-major, tf32-rounded
__device__ float g_bqk[128];

// ======================= helpers ==========================================
__device__ __forceinline__ uint32_t f2tf32(float f) {
    uint32_t o;
    asm("cvt.rna.tf32.f32 %0, %1;" : "=r"(o) : "f"(f));
    return o;
}
__device__ __forceinline__ float rtf(float f) { return __uint_as_float(f2tf32(f)); }

__device__ __forceinline__ uint32_t smem_u32(const void* p) {
    uint32_t a;
    asm("{ .reg .u64 t; cvta.to.shared.u64 t, %1; cvt.u32.u64 %0, t; }"
        : "=r"(a) : "l"(p));
    return a;
}
__device__ __forceinline__ void cpa16(uint32_t dst, const float* src) {
    asm volatile("cp.async.cg.shared.global [%0], [%1], 16;"
                 :: "r"(dst), "l"(src));
}
#define CP_COMMIT() asm volatile("cp.async.commit_group;" ::: "memory")
#define CP_WAIT0()  asm volatile("cp.async.wait_group 0;" ::: "memory")

// XOR-swizzled word index inside a 128x16-word tile (conflict-free frags)
__device__ __forceinline__ int swz(int m, int k) {
    return (m << 4) + ((((k >> 2) ^ ((m >> 1) & 3)) << 2)) + (k & 3);
}

__device__ __forceinline__ void mma_tf32(float c[4], const uint32_t a[4],
                                         const uint32_t b[2]) {
    asm volatile(
        "mma.sync.aligned.m16n8k8.row.col.f32.tf32.tf32.f32 "
        "{%0,%1,%2,%3}, {%4,%5,%6,%7}, {%8,%9}, {%0,%1,%2,%3};"
        : "+f"(c[0]), "+f"(c[1]), "+f"(c[2]), "+f"(c[3])
        : "r"(a[0]), "r"(a[1]), "r"(a[2]), "r"(a[3]), "r"(b[0]), "r"(b[1]));
}

// ===========================================================================
// Prep kernels
// ===========================================================================
__global__ __launch_bounds__(256) void round_x_kernel(const float* __restrict__ X)
{
    size_t i = (size_t)blockIdx.x * 256 + threadIdx.x;
    float4 v = reinterpret_cast<const float4*>(X)[i];
    float4 o = {rtf(v.x), rtf(v.y), rtf(v.z), rtf(v.w)};
    reinterpret_cast<float4*>(g_Xt)[i] = o;
}

__global__ __launch_bounds__(256) void transpose_wv_kernel(const float* __restrict__ Wv)
{
    __shared__ float t[32][33];
    const int k0 = blockIdx.x * 32, n0 = blockIdx.y * 32;
    const int tx = threadIdx.x, ty = threadIdx.y;
#pragma unroll
    for (int i = 0; i < 32; i += 8)
        t[ty + i][tx] = Wv[(k0 + ty + i) * DM + n0 + tx];
    __syncthreads();
#pragma unroll
    for (int i = 0; i < 32; i += 8)
        g_WvT[(n0 + ty + i) * DM + k0 + tx] = rtf(t[tx][ty + i]);
}

__global__ __launch_bounds__(256) void prep_qk_kernel(
    const float* __restrict__ Wq, const float* __restrict__ bq,
    const float* __restrict__ Wk, const float* __restrict__ bk)
{
    __shared__ float t[32][33];
    const int k0 = blockIdx.x * 32, n0 = blockIdx.y * 32;
    const int tx = threadIdx.x, ty = threadIdx.y;
    const int n = n0 + tx;
#pragma unroll
    for (int i = 0; i < 32; i += 8) {
        int k = k0 + ty + i;
        t[ty + i][tx] = (n < 64) ? Wq[k * DK + n] : Wk[k * DK + (n - 64)];
    }
    __syncthreads();
#pragma unroll
    for (int i = 0; i < 32; i += 8)
        g_WqkT[(n0 + ty + i) * DM + k0 + tx] = rtf(t[tx][ty + i]);
    if (blockIdx.x == 0 && blockIdx.y == 0) {
        int id = ty * 32 + tx;
        if (id < 128) g_bqk[id] = (id < 64) ? bq[id] : bk[id - 64];
    }
}

// ===========================================================================
// tf32 mma.sync GEMM (projections) with cp.async double buffering.
// A = g_Xt.  mode 0: Bt=g_WvT -> g_V (+bv, rounded).  mode 1: Bt=g_WqkT ->
// g_Q|g_K (+g_bqk, rounded).  BM=128 BN=128 BK=16, 8 warps 2x4, warp 64x32.
// ===========================================================================
__global__ __launch_bounds__(256, 2) void gemm_tc_kernel(
    const float* __restrict__ bv, int mode)
{
    __shared__ uint32_t sA[2][2048];   // 8 KB each buf
    __shared__ uint32_t sB[2][2048];

    const float* A  = g_Xt;
    const float* Bt = mode ? g_WqkT : g_WvT;

    const int r0   = blockIdx.x * 128;
    const int nc   = blockIdx.y * 128;
    const int tid  = threadIdx.x;
    const int wid  = tid >> 5;
    const int lane = tid & 31;
    const int wm   = (wid >> 2) * 64;
    const int wn   = (wid & 3) * 32;
    const int lr   = lane >> 2;
    const int lc   = lane & 3;

    // per-thread cp.async slots (2 chunks per operand)
    const int cm = tid >> 2, cc = tid & 3;
    uint32_t dA[2], dB[2];
    const float *pA[2], *pB[2];
#pragma unroll
    for (int it = 0; it < 2; it++) {
        int m = cm + it * 64;
        int w = (m << 4) + (((cc ^ ((m >> 1) & 3))) << 2);
        dA[it] = smem_u32(&sA[0][0]) + 4 * w;
        dB[it] = smem_u32(&sB[0][0]) + 4 * w;
        pA[it] = A  + (size_t)(r0 + m) * DM + cc * 4;
        pB[it] = Bt + (size_t)(nc + m) * DM + cc * 4;
    }

    float acc[4][4][4];
#pragma unroll
    for (int mi = 0; mi < 4; mi++)
#pragma unroll
        for (int ni = 0; ni < 4; ni++)
#pragma unroll
            for (int r = 0; r < 4; r++) acc[mi][ni][r] = 0.f;

#pragma unroll
    for (int it = 0; it < 2; it++) { cpa16(dA[it], pA[it]); cpa16(dB[it], pB[it]); }
    CP_COMMIT();

    int cur = 0;
    const int NT = DM / 16;
    for (int kt = 0; kt < NT; kt++) {
        CP_WAIT0();
        __syncthreads();
        if (kt + 1 < NT) {
            const int kc = (kt + 1) * 16;
            const uint32_t off = (cur ^ 1) * 8192u;
#pragma unroll
            for (int it = 0; it < 2; it++) {
                cpa16(dA[it] + off, pA[it] + kc);
                cpa16(dB[it] + off, pB[it] + kc);
            }
            CP_COMMIT();
        }
        const uint32_t* cA = sA[cur];
        const uint32_t* cB = sB[cur];
#pragma unroll
        for (int ks = 0; ks < 2; ks++) {
            const int k0 = ks * 8;
            uint32_t a[4][4], b[4][2];
#pragma unroll
            for (int mi = 0; mi < 4; mi++) {
                int row = wm + mi * 16 + lr;
                a[mi][0] = cA[swz(row,     k0 + lc)];
                a[mi][1] = cA[swz(row + 8, k0 + lc)];
                a[mi][2] = cA[swz(row,     k0 + lc + 4)];
                a[mi][3] = cA[swz(row + 8, k0 + lc + 4)];
            }
#pragma unroll
            for (int ni = 0; ni < 4; ni++) {
                int n = wn + ni * 8 + lr;
                b[ni][0] = cB[swz(n, k0 + lc)];
                b[ni][1] = cB[swz(n, k0 + lc + 4)];
            }
#pragma unroll
            for (int mi = 0; mi < 4; mi++)
#pragma unroll
                for (int ni = 0; ni < 4; ni++)
                    mma_tf32(acc[mi][ni], a[mi], b[ni]);
        }
        cur ^= 1;
    }

    // epilogue: bias add in fp32, store tf32-rounded (consumers feed raw bits)
#pragma unroll
    for (int mi = 0; mi < 4; mi++) {
#pragma unroll
        for (int ni = 0; ni < 4; ni++) {
#pragma unroll
            for (int h = 0; h < 2; h++) {
                int row = r0 + wm + mi * 16 + lr + h * 8;
                int col = wn + ni * 8 + 2 * lc;
                float v0 = acc[mi][ni][h * 2 + 0];
                float v1 = acc[mi][ni][h * 2 + 1];
                if (mode == 0) {
                    float2 o = {rtf(v0 + bv[nc + col]), rtf(v1 + bv[nc + col + 1])};
                    *reinterpret_cast<float2*>(&g_V[(size_t)row * DM + nc + col]) = o;
                } else {
                    float2 o = {rtf(v0 + g_bqk[col]), rtf(v1 + g_bqk[col + 1])};
                    if (col < 64)
                        *reinterpret_cast<float2*>(&g_Q[(size_t)row * DK + col]) = o;
                    else
                        *reinterpret_cast<float2*>(&g_K[(size_t)row * DK + (col - 64)]) = o;
                }
            }
        }
    }
}

// ===========================================================================
// score_kernel: one 128x128 causal tile of S = Q K^T / 8 per CTA (raw fp32,
// masked = -1e30).  cp.async double-buffered, NT = 4 (DK=64, BK=16).
// ===========================================================================
__global__ __launch_bounds__(256, 2) void score_kernel()
{
    __shared__ uint32_t sA[2][2048];
    __shared__ uint32_t sB[2][2048];

    int i = blockIdx.x;
    int qt = (int)((sqrtf(8.f * (float)i + 1.f) - 1.f) * 0.5f);
    while ((qt + 1) * (qt + 2) / 2 <= i) qt++;
    while (qt * (qt + 1) / 2 > i) qt--;
    const int kt = i - qt * (qt + 1) / 2;

    const int b     = blockIdx.y;
    const int qbase = b * S + qt * 128;
    const int kbase = b * S + kt * 128;

    const int tid  = threadIdx.x;
    const int wid  = tid >> 5;
    const int lane = tid & 31;
    const int wm   = (wid >> 2) * 64;
    const int wn   = (wid & 3) * 32;
    const int lr   = lane >> 2;
    const int lc   = lane & 3;

    const int cm = tid >> 2, cc = tid & 3;
    uint32_t dA[2], dB[2];
    const float *pA[2], *pB[2];
#pragma unroll
    for (int it = 0; it < 2; it++) {
        int m = cm + it * 64;
        int w = (m << 4) + (((cc ^ ((m >> 1) & 3))) << 2);
        dA[it] = smem_u32(&sA[0][0]) + 4 * w;
        dB[it] = smem_u32(&sB[0][0]) + 4 * w;
        pA[it] = g_Q + (size_t)(qbase + m) * DK + cc * 4;
        pB[it] = g_K + (size_t)(kbase + m) * DK + cc * 4;
    }

    float acc[4][4][4];
#pragma unroll
    for (int mi = 0; mi < 4; mi++)
#pragma unroll
        for (int ni = 0; ni < 4; ni++)
#pragma unroll
            for (int r = 0; r < 4; r++) acc[mi][ni][r] = 0.f;

#pragma unroll
    for (int it = 0; it < 2; it++) { cpa16(dA[it], pA[it]); cpa16(dB[it], pB[it]); }
    CP_COMMIT();

    int cur = 0;
    const int NT = DK / 16;
    for (int ktile = 0; ktile < NT; ktile++) {
        CP_WAIT0();
        __syncthreads();
        if (ktile + 1 < NT) {
            const int kc = (ktile + 1) * 16;
            const uint32_t off = (cur ^ 1) * 8192u;
#pragma unroll
            for (int it = 0; it < 2; it++) {
                cpa16(dA[it] + off, pA[it] + kc);
                cpa16(dB[it] + off, pB[it] + kc);
            }
            CP_COMMIT();
        }
        const uint32_t* cA = sA[cur];
        const uint32_t* cB = sB[cur];
#pragma unroll
        for (int ks = 0; ks < 2; ks++) {
            const int k0 = ks * 8;
            uint32_t a[4][4], b2[4][2];
#pragma unroll
            for (int mi = 0; mi < 4; mi++) {
                int row = wm + mi * 16 + lr;
                a[mi][0] = cA[swz(row,     k0 + lc)];
                a[mi][1] = cA[swz(row + 8, k0 + lc)];
                a[mi][2] = cA[swz(row,     k0 + lc + 4)];
                a[mi][3] = cA[swz(row + 8, k0 + lc + 4)];
            }
#pragma unroll
            for (int ni = 0; ni < 4; ni++) {
                int n = wn + ni * 8 + lr;
                b2[ni][0] = cB[swz(n, k0 + lc)];
                b2[ni][1] = cB[swz(n, k0 + lc + 4)];
            }
#pragma unroll
            for (int mi = 0; mi < 4; mi++)
#pragma unroll
                for (int ni = 0; ni < 4; ni++)
                    mma_tf32(acc[mi][ni], a[mi], b2[ni]);
        }
        cur ^= 1;
    }

#pragma unroll
    for (int mi = 0; mi < 4; mi++) {
#pragma unroll
        for (int ni = 0; ni < 4; ni++) {
#pragma unroll
            for (int h = 0; h < 2; h++) {
                int qrow = qt * 128 + wm + mi * 16 + lr + h * 8;
                int kcol = kt * 128 + wn + ni * 8 + 2 * lc;
                float v0 = acc[mi][ni][h * 2 + 0] * 0.125f;
                float v1 = acc[mi][ni][h * 2 + 1] * 0.125f;
                if (kcol > qrow)     v0 = -1e30f;
                if (kcol + 1 > qrow) v1 = -1e30f;
                float2 o = {v0, v1};
                *reinterpret_cast<float2*>(
                    &g_P[(size_t)(b * S + qrow) * S + kcol]) = o;
            }
        }
    }
}

// ===========================================================================
// rowexp_kernel: warp per row, branch-free float4; stores tf32-rounded probs.
// ===========================================================================
__global__ __launch_bounds__(256) void rowexp_kernel()
{
    const int tid  = threadIdx.x;
    const int wid  = tid >> 5;
    const int lane = tid & 31;
    const int row  = blockIdx.x * 8 + wid;
    const int q    = row & (S - 1);
    float4* P4 = reinterpret_cast<float4*>(&g_P[(size_t)row * S]);
    const int n4 = (((q >> 7) + 1) << 7) >> 2;

    float m = -1e30f;
    for (int j = lane; j < n4; j += 32) {
        float4 v = P4[j];
        m = fmaxf(m, fmaxf(fmaxf(v.x, v.y), fmaxf(v.z, v.w)));
    }
#pragma unroll
    for (int off = 16; off > 0; off >>= 1)
        m = fmaxf(m, __shfl_xor_sync(0xffffffffu, m, off));

    float l = 0.f;
    for (int j = lane; j < n4; j += 32) {
        float4 v = P4[j];
        float ex = __expf(v.x - m), ey = __expf(v.y - m);
        float ez = __expf(v.z - m), ew = __expf(v.w - m);
        l += (ex + ey) + (ez + ew);
        float4 e = {rtf(ex), rtf(ey), rtf(ez), rtf(ew)};
        P4[j] = e;
    }
#pragma unroll
    for (int off = 16; off > 0; off >>= 1)
        l += __shfl_xor_sync(0xffffffffu, l, off);

    if (lane == 0) g_L[row] = l;
}

// ===========================================================================
// pv_kernel: O[128q x 128d] = (P/l) @ V, causal k-loop, cp.async both tiles.
// BM=128 BN=128 BK=16, 256 thr, 8 warps 2x4, warp 64x32.
// sP swizzled 128x16; sV [k][d] stride 136 words (conflict-free).
// ===========================================================================
__global__ __launch_bounds__(256, 2) void pv_kernel(float* __restrict__ out)
{
    __shared__ uint32_t sP[2][2048];
    __shared__ uint32_t sV[2][16 * 136];

    const int qt    = blockIdx.x;
    const int dc0   = blockIdx.y * 128;
    const int b     = blockIdx.z;
    const int base  = b * S;
    const int qbase = base + qt * 128;

    const int tid  = threadIdx.x;
    const int wid  = tid >> 5;
    const int lane = tid & 31;
    const int wm   = (wid >> 2) * 64;
    const int wn   = (wid & 3) * 32;
    const int lr   = lane >> 2;
    const int lc   = lane & 3;

    // cp.async slots: P 2 chunks/thread, V 2 chunks/thread
    const int cm = tid >> 2, cc = tid & 3;
    uint32_t dP[2], dV[2];
    const float *pP[2], *pV[2];
#pragma unroll
    for (int it = 0; it < 2; it++) {
        int m = cm + it * 64;
        int w = (m << 4) + (((cc ^ ((m >> 1) & 3))) << 2);
        dP[it] = smem_u32(&sP[0][0]) + 4 * w;
        pP[it] = g_P + (size_t)(qbase + m) * S + cc * 4;
        int lin = tid + it * 256;
        int k = lin >> 5, c = lin & 31;
        dV[it] = smem_u32(&sV[0][0]) + 4 * (k * 136 + c * 4);
        pV[it] = g_V + (size_t)(base + k) * DM + dc0 + c * 4;
    }

    float acc[4][4][4];
#pragma unroll
    for (int mi = 0; mi < 4; mi++)
#pragma unroll
        for (int ni = 0; ni < 4; ni++)
#pragma unroll
            for (int r = 0; r < 4; r++) acc[mi][ni][r] = 0.f;

#pragma unroll
    for (int it = 0; it < 2; it++) { cpa16(dP[it], pP[it]); cpa16(dV[it], pV[it]); }
    CP_COMMIT();

    int cur = 0;
    const int NT = (qt + 1) * 8;
    for (int kt = 0; kt < NT; kt++) {
        CP_WAIT0();
        __syncthreads();
        if (kt + 1 < NT) {
            const int kc = (kt + 1) * 16;
            const uint32_t offP = (cur ^ 1) * 8192u;
            const uint32_t offV = (cur ^ 1) * (16u * 136u * 4u);
#pragma unroll
            for (int it = 0; it < 2; it++) {
                cpa16(dP[it] + offP, pP[it] + kc);
                cpa16(dV[it] + offV, pV[it] + (size_t)kc * DM);
            }
            CP_COMMIT();
        }
        const uint32_t* cP = sP[cur];
        const uint32_t* cV = sV[cur];
#pragma unroll
        for (int ks = 0; ks < 2; ks++) {
            const int k0 = ks * 8;
            uint32_t a[4][4], b2[4][2];
#pragma unroll
            for (int mi = 0; mi < 4; mi++) {
                int row = wm + mi * 16 + lr;
                a[mi][0] = cP[swz(row,     k0 + lc)];
                a[mi][1] = cP[swz(row + 8, k0 + lc)];
                a[mi][2] = cP[swz(row,     k0 + lc + 4)];
                a[mi][3] = cP[swz(row + 8, k0 + lc + 4)];
            }
#pragma unroll
            for (int ni = 0; ni < 4; ni++) {
                int n = wn + ni * 8 + lr;
                b2[ni][0] = cV[(k0 + lc) * 136 + n];
                b2[ni][1] = cV[(k0 + lc + 4) * 136 + n];
            }
#pragma unroll
            for (int mi = 0; mi < 4; mi++)
#pragma unroll
                for (int ni = 0; ni < 4; ni++)
                    mma_tf32(acc[mi][ni], a[mi], b2[ni]);
        }
        cur ^= 1;
    }

#pragma unroll
    for (int mi = 0; mi < 4; mi++) {
#pragma unroll
        for (int h = 0; h < 2; h++) {
            int qrow = qt * 128 + wm + mi * 16 + lr + h * 8;
            float linv = 1.0f / g_L[base + qrow];
#pragma unroll
            for (int ni = 0; ni < 4; ni++) {
                int col = dc0 + wn + ni * 8 + 2 * lc;
                float2 o = {acc[mi][ni][h * 2 + 0] * linv,
                            acc[mi][ni][h * 2 + 1] * linv};
                *reinterpret_cast<float2*>(
                    &out[(size_t)(base + qrow) * DM + col]) = o;
            }
        }
    }
}

// ===========================================================================
extern "C" void kernel_launch(void* const* d_in, const int* in_sizes, int n_in,
                              void* d_out, int out_size)
{
    const float* X  = (const float*)d_in[0];
    const float* Wq = (const float*)d_in[1];
    const float* bq = (const float*)d_in[2];
    const float* Wk = (const float*)d_in[3];
    const float* bk = (const float*)d_in[4];
    const float* Wv = (const float*)d_in[5];
    const float* bv = (const float*)d_in[6];
    float* out = (float*)d_out;

    round_x_kernel<<<(size_t)ROWS * DM / 4 / 256, 256>>>(X);
    transpose_wv_kernel<<<dim3(32, 32), dim3(32, 8)>>>(Wv);
    prep_qk_kernel<<<dim3(32, 4), dim3(32, 8)>>>(Wq, bq, Wk, bk);
    gemm_tc_kernel<<<dim3(128, 1), 256>>>(nullptr, 1);      // Q|K projection
    gemm_tc_kernel<<<dim3(128, 8), 256>>>(bv, 0);           // V projection
    score_kernel<<<dim3(136, 8), 256>>>();                  // S = QK^T/8 (causal)
    rowexp_kernel<<<ROWS / 8, 256>>>();                     // softmax (in place)
    pv_kernel<<<dim3(S / 128, DM / 128, B), 256>>>(out);    // O = P V / l
}

// round 12
// speedup vs baseline: 1.3423x; 1.0597x over previous
#include <cuda_runtime.h>
#include <cstdint>

#define B 8
#define S 2048
#define DM 1024
#define DK 64
#define ROWS (B * S)

// ---------------- scratch (device globals; no allocation allowed) ----------
__device__ float g_Xt[(size_t)ROWS * DM];   // X, tf32-rounded (64 MB)
__device__ float g_Q[ROWS * DK];            // tf32-rounded
__device__ float g_K[ROWS * DK];            // tf32-rounded
__device__ float g_V[ROWS * DM];            // tf32-rounded (64 MB)
__device__ float g_L[ROWS];
__device__ float g_P[(size_t)ROWS * S];     // scores, then tf32-rounded probs
__device__ float g_WvT[DM * DM];            // Wv^T, K-major, tf32-rounded
__device__ float g_WqkT[128 * DM];          // [Wq|Wk]^T, K-major, tf32-rounded
__device__ float g_bqk[128];

// ======================= helpers ==========================================
__device__ __forceinline__ uint32_t f2tf32(float f) {
    uint32_t o;
    asm("cvt.rna.tf32.f32 %0, %1;" : "=r"(o) : "f"(f));
    return o;
}
__device__ __forceinline__ float rtf(float f) { return __uint_as_float(f2tf32(f)); }

__device__ __forceinline__ uint32_t smem_u32(const void* p) {
    uint32_t a;
    asm("{ .reg .u64 t; cvta.to.shared.u64 t, %1; cvt.u32.u64 %0, t; }"
        : "=r"(a) : "l"(p));
    return a;
}
__device__ __forceinline__ void cpa16(uint32_t dst, const float* src) {
    asm volatile("cp.async.cg.shared.global [%0], [%1], 16;"
                 :: "r"(dst), "l"(src));
}
#define CP_COMMIT() asm volatile("cp.async.commit_group;" ::: "memory")
#define CP_WAIT1()  asm volatile("cp.async.wait_group 1;" ::: "memory")

// XOR-swizzled word index inside a 128x16-word tile (conflict-free frags)
__device__ __forceinline__ int swz(int m, int k) {
    return (m << 4) + ((((k >> 2) ^ ((m >> 1) & 3)) << 2)) + (k & 3);
}
// V-tile swizzle: 16 rows x 128 words, flip word-index bits 3-4 by (k&3)
__device__ __forceinline__ int vswz(int k, int d) {
    return (k << 7) + (d ^ ((k & 3) << 3));
}

__device__ __forceinline__ void mma_tf32(float c[4], const uint32_t a[4],
                                         const uint32_t b[2]) {
    asm volatile(
        "mma.sync.aligned.m16n8k8.row.col.f32.tf32.tf32.f32 "
        "{%0,%1,%2,%3}, {%4,%5,%6,%7}, {%8,%9}, {%0,%1,%2,%3};"
        : "+f"(c[0]), "+f"(c[1]), "+f"(c[2]), "+f"(c[3])
        : "r"(a[0]), "r"(a[1]), "r"(a[2]), "r"(a[3]), "r"(b[0]), "r"(b[1]));
}

// ===========================================================================
// Prep kernels
// ===========================================================================
__global__ __launch_bounds__(256) void round_x_kernel(const float* __restrict__ X)
{
    size_t i = (size_t)blockIdx.x * 256 + threadIdx.x;
    float4 v = reinterpret_cast<const float4*>(X)[i];
    float4 o = {rtf(v.x), rtf(v.y), rtf(v.z), rtf(v.w)};
    reinterpret_cast<float4*>(g_Xt)[i] = o;
}

__global__ __launch_bounds__(256) void transpose_wv_kernel(const float* __restrict__ Wv)
{
    __shared__ float t[32][33];
    const int k0 = blockIdx.x * 32, n0 = blockIdx.y * 32;
    const int tx = threadIdx.x, ty = threadIdx.y;
#pragma unroll
    for (int i = 0; i < 32; i += 8)
        t[ty + i][tx] = Wv[(k0 + ty + i) * DM + n0 + tx];
    __syncthreads();
#pragma unroll
    for (int i = 0; i < 32; i += 8)
        g_WvT[(n0 + ty + i) * DM + k0 + tx] = rtf(t[tx][ty + i]);
}

__global__ __launch_bounds__(256) void prep_qk_kernel(
    const float* __restrict__ Wq, const float* __restrict__ bq,
    const float* __restrict__ Wk, const float* __restrict__ bk)
{
    __shared__ float t[32][33];
    const int k0 = blockIdx.x * 32, n0 = blockIdx.y * 32;
    const int tx = threadIdx.x, ty = threadIdx.y;
    const int n = n0 + tx;
#pragma unroll
    for (int i = 0; i < 32; i += 8) {
        int k = k0 + ty + i;
        t[ty + i][tx] = (n < 64) ? Wq[k * DK + n] : Wk[k * DK + (n - 64)];
    }
    __syncthreads();
#pragma unroll
    for (int i = 0; i < 32; i += 8)
        g_WqkT[(n0 + ty + i) * DM + k0 + tx] = rtf(t[tx][ty + i]);
    if (blockIdx.x == 0 && blockIdx.y == 0) {
        int id = ty * 32 + tx;
        if (id < 128) g_bqk[id] = (id < 64) ? bq[id] : bk[id - 64];
    }
}

// ===========================================================================
// tf32 mma.sync GEMM (projections), 3-stage cp.async ring.
// A = g_Xt.  mode 0: Bt=g_WvT -> g_V (+bv, rounded).  mode 1: Bt=g_WqkT ->
// g_Q|g_K (+g_bqk, rounded).  BM=128 BN=128 BK=16, 8 warps 2x4, warp 64x32.
// ===========================================================================
__global__ __launch_bounds__(256, 2) void gemm_tc_kernel(
    const float* __restrict__ bv, int mode)
{
    __shared__ uint32_t sA[3][2048];   // 24 KB
    __shared__ uint32_t sB[3][2048];   // 24 KB

    const float* A  = g_Xt;
    const float* Bt = mode ? g_WqkT : g_WvT;

    const int r0   = blockIdx.x * 128;
    const int nc   = blockIdx.y * 128;
    const int tid  = threadIdx.x;
    const int wid  = tid >> 5;
    const int lane = tid & 31;
    const int wm   = (wid >> 2) * 64;
    const int wn   = (wid & 3) * 32;
    const int lr   = lane >> 2;
    const int lc   = lane & 3;

    const int cm = tid >> 2, cc = tid & 3;
    uint32_t dA[2], dB[2];
    const float *pA[2], *pB[2];
#pragma unroll
    for (int it = 0; it < 2; it++) {
        int m = cm + it * 64;
        int w = (m << 4) + (((cc ^ ((m >> 1) & 3))) << 2);
        dA[it] = smem_u32(&sA[0][0]) + 4 * w;
        dB[it] = smem_u32(&sB[0][0]) + 4 * w;
        pA[it] = A  + (size_t)(r0 + m) * DM + cc * 4;
        pB[it] = Bt + (size_t)(nc + m) * DM + cc * 4;
    }

    float acc[4][4][4];
#pragma unroll
    for (int mi = 0; mi < 4; mi++)
#pragma unroll
        for (int ni = 0; ni < 4; ni++)
#pragma unroll
            for (int r = 0; r < 4; r++) acc[mi][ni][r] = 0.f;

    const int NT = DM / 16;
    // prologue: tiles 0 and 1, one group each
#pragma unroll
    for (int t = 0; t < 2; t++) {
        const uint32_t off = t * 8192u;
        const int kc = t * 16;
#pragma unroll
        for (int it = 0; it < 2; it++) {
            cpa16(dA[it] + off, pA[it] + kc);
            cpa16(dB[it] + off, pB[it] + kc);
        }
        CP_COMMIT();
    }

    int cur = 0;                 // stage of tile kt
    for (int kt = 0; kt < NT; kt++) {
        CP_WAIT1();
        __syncthreads();
        {
            int nx = cur + 2; if (nx >= 3) nx -= 3;
            if (kt + 2 < NT) {
                const int kc = (kt + 2) * 16;
                const uint32_t off = nx * 8192u;
#pragma unroll
                for (int it = 0; it < 2; it++) {
                    cpa16(dA[it] + off, pA[it] + kc);
                    cpa16(dB[it] + off, pB[it] + kc);
                }
            }
            CP_COMMIT();   // always (empty groups keep FIFO uniform)
        }
        const uint32_t* cA = sA[cur];
        const uint32_t* cB = sB[cur];
#pragma unroll
        for (int ks = 0; ks < 2; ks++) {
            const int k0 = ks * 8;
            uint32_t a[4][4], b[4][2];
#pragma unroll
            for (int mi = 0; mi < 4; mi++) {
                int row = wm + mi * 16 + lr;
                a[mi][0] = cA[swz(row,     k0 + lc)];
                a[mi][1] = cA[swz(row + 8, k0 + lc)];
                a[mi][2] = cA[swz(row,     k0 + lc + 4)];
                a[mi][3] = cA[swz(row + 8, k0 + lc + 4)];
            }
#pragma unroll
            for (int ni = 0; ni < 4; ni++) {
                int n = wn + ni * 8 + lr;
                b[ni][0] = cB[swz(n, k0 + lc)];
                b[ni][1] = cB[swz(n, k0 + lc + 4)];
            }
#pragma unroll
            for (int mi = 0; mi < 4; mi++)
#pragma unroll
                for (int ni = 0; ni < 4; ni++)
                    mma_tf32(acc[mi][ni], a[mi], b[ni]);
        }
        cur++; if (cur >= 3) cur = 0;
    }

#pragma unroll
    for (int mi = 0; mi < 4; mi++) {
#pragma unroll
        for (int ni = 0; ni < 4; ni++) {
#pragma unroll
            for (int h = 0; h < 2; h++) {
                int row = r0 + wm + mi * 16 + lr + h * 8;
                int col = wn + ni * 8 + 2 * lc;
                float v0 = acc[mi][ni][h * 2 + 0];
                float v1 = acc[mi][ni][h * 2 + 1];
                if (mode == 0) {
                    float2 o = {rtf(v0 + bv[nc + col]), rtf(v1 + bv[nc + col + 1])};
                    *reinterpret_cast<float2*>(&g_V[(size_t)row * DM + nc + col]) = o;
                } else {
                    float2 o = {rtf(v0 + g_bqk[col]), rtf(v1 + g_bqk[col + 1])};
                    if (col < 64)
                        *reinterpret_cast<float2*>(&g_Q[(size_t)row * DK + col]) = o;
                    else
                        *reinterpret_cast<float2*>(&g_K[(size_t)row * DK + (col - 64)]) = o;
                }
            }
        }
    }
}

// ===========================================================================
// score_kernel: one 128x128 causal tile of S = Q K^T / 8 per CTA (raw fp32,
// masked = -1e30).  3-stage ring, NT = 4 (DK=64, BK=16).
// ===========================================================================
__global__ __launch_bounds__(256, 2) void score_kernel()
{
    __shared__ uint32_t sA[3][2048];
    __shared__ uint32_t sB[3][2048];

    int i = blockIdx.x;
    int qt = (int)((sqrtf(8.f * (float)i + 1.f) - 1.f) * 0.5f);
    while ((qt + 1) * (qt + 2) / 2 <= i) qt++;
    while (qt * (qt + 1) / 2 > i) qt--;
    const int kt = i - qt * (qt + 1) / 2;

    const int b     = blockIdx.y;
    const int qbase = b * S + qt * 128;
    const int kbase = b * S + kt * 128;

    const int tid  = threadIdx.x;
    const int wid  = tid >> 5;
    const int lane = tid & 31;
    const int wm   = (wid >> 2) * 64;
    const int wn   = (wid & 3) * 32;
    const int lr   = lane >> 2;
    const int lc   = lane & 3;

    const int cm = tid >> 2, cc = tid & 3;
    uint32_t dA[2], dB[2];
    const float *pA[2], *pB[2];
#pragma unroll
    for (int it = 0; it < 2; it++) {
        int m = cm + it * 64;
        int w = (m << 4) + (((cc ^ ((m >> 1) & 3))) << 2);
        dA[it] = smem_u32(&sA[0][0]) + 4 * w;
        dB[it] = smem_u32(&sB[0][0]) + 4 * w;
        pA[it] = g_Q + (size_t)(qbase + m) * DK + cc * 4;
        pB[it] = g_K + (size_t)(kbase + m) * DK + cc * 4;
    }

    float acc[4][4][4];
#pragma unroll
    for (int mi = 0; mi < 4; mi++)
#pragma unroll
        for (int ni = 0; ni < 4; ni++)
#pragma unroll
            for (int r = 0; r < 4; r++) acc[mi][ni][r] = 0.f;

    const int NT = DK / 16;   // 4
#pragma unroll
    for (int t = 0; t < 2; t++) {
        const uint32_t off = t * 8192u;
        const int kc = t * 16;
#pragma unroll
        for (int it = 0; it < 2; it++) {
            cpa16(dA[it] + off, pA[it] + kc);
            cpa16(dB[it] + off, pB[it] + kc);
        }
        CP_COMMIT();
    }

    int cur = 0;
    for (int ktile = 0; ktile < NT; ktile++) {
        CP_WAIT1();
        __syncthreads();
        {
            int nx = cur + 2; if (nx >= 3) nx -= 3;
            if (ktile + 2 < NT) {
                const int kc = (ktile + 2) * 16;
                const uint32_t off = nx * 8192u;
#pragma unroll
                for (int it = 0; it < 2; it++) {
                    cpa16(dA[it] + off, pA[it] + kc);
                    cpa16(dB[it] + off, pB[it] + kc);
                }
            }
            CP_COMMIT();
        }
        const uint32_t* cA = sA[cur];
        const uint32_t* cB = sB[cur];
#pragma unroll
        for (int ks = 0; ks < 2; ks++) {
            const int k0 = ks * 8;
            uint32_t a[4][4], b2[4][2];
#pragma unroll
            for (int mi = 0; mi < 4; mi++) {
                int row = wm + mi * 16 + lr;
                a[mi][0] = cA[swz(row,     k0 + lc)];
                a[mi][1] = cA[swz(row + 8, k0 + lc)];
                a[mi][2] = cA[swz(row,     k0 + lc + 4)];
                a[mi][3] = cA[swz(row + 8, k0 + lc + 4)];
            }
#pragma unroll
            for (int ni = 0; ni < 4; ni++) {
                int n = wn + ni * 8 + lr;
                b2[ni][0] = cB[swz(n, k0 + lc)];
                b2[ni][1] = cB[swz(n, k0 + lc + 4)];
            }
#pragma unroll
            for (int mi = 0; mi < 4; mi++)
#pragma unroll
                for (int ni = 0; ni < 4; ni++)
                    mma_tf32(acc[mi][ni], a[mi], b2[ni]);
        }
        cur++; if (cur >= 3) cur = 0;
    }

#pragma unroll
    for (int mi = 0; mi < 4; mi++) {
#pragma unroll
        for (int ni = 0; ni < 4; ni++) {
#pragma unroll
            for (int h = 0; h < 2; h++) {
                int qrow = qt * 128 + wm + mi * 16 + lr + h * 8;
                int kcol = kt * 128 + wn + ni * 8 + 2 * lc;
                float v0 = acc[mi][ni][h * 2 + 0] * 0.125f;
                float v1 = acc[mi][ni][h * 2 + 1] * 0.125f;
                if (kcol > qrow)     v0 = -1e30f;
                if (kcol + 1 > qrow) v1 = -1e30f;
                float2 o = {v0, v1};
                *reinterpret_cast<float2*>(
                    &g_P[(size_t)(b * S + qrow) * S + kcol]) = o;
            }
        }
    }
}

// ===========================================================================
// rowexp_kernel: warp per row, branch-free float4; stores tf32-rounded probs.
// ===========================================================================
__global__ __launch_bounds__(256) void rowexp_kernel()
{
    const int tid  = threadIdx.x;
    const int wid  = tid >> 5;
    const int lane = tid & 31;
    const int row  = blockIdx.x * 8 + wid;
    const int q    = row & (S - 1);
    float4* P4 = reinterpret_cast<float4*>(&g_P[(size_t)row * S]);
    const int n4 = (((q >> 7) + 1) << 7) >> 2;

    float m = -1e30f;
    for (int j = lane; j < n4; j += 32) {
        float4 v = P4[j];
        m = fmaxf(m, fmaxf(fmaxf(v.x, v.y), fmaxf(v.z, v.w)));
    }
#pragma unroll
    for (int off = 16; off > 0; off >>= 1)
        m = fmaxf(m, __shfl_xor_sync(0xffffffffu, m, off));

    float l = 0.f;
    for (int j = lane; j < n4; j += 32) {
        float4 v = P4[j];
        float ex = __expf(v.x - m), ey = __expf(v.y - m);
        float ez = __expf(v.z - m), ew = __expf(v.w - m);
        l += (ex + ey) + (ez + ew);
        float4 e = {rtf(ex), rtf(ey), rtf(ez), rtf(ew)};
        P4[j] = e;
    }
#pragma unroll
    for (int off = 16; off > 0; off >>= 1)
        l += __shfl_xor_sync(0xffffffffu, l, off);

    if (lane == 0) g_L[row] = l;
}

// ===========================================================================
// pv_kernel: O[128q x 128d] = (P/l) @ V, causal k-loop, 3-stage ring.
// BM=128 BN=128 BK=16, 256 thr, 8 warps 2x4, warp 64x32.
// sP swizzled 128x16; sV 16x128 with vswz (conflict-free, 8KB/stage).
// ===========================================================================
__global__ __launch_bounds__(256, 2) void pv_kernel(float* __restrict__ out)
{
    __shared__ uint32_t sP[3][2048];
    __shared__ uint32_t sV[3][2048];

    const int qt    = blockIdx.x;
    const int dc0   = blockIdx.y * 128;
    const int b     = blockIdx.z;
    const int base  = b * S;
    const int qbase = base + qt * 128;

    const int tid  = threadIdx.x;
    const int wid  = tid >> 5;
    const int lane = tid & 31;
    const int wm   = (wid >> 2) * 64;
    const int wn   = (wid & 3) * 32;
    const int lr   = lane >> 2;
    const int lc   = lane & 3;

    const int cm = tid >> 2, cc = tid & 3;
    uint32_t dP[2], dV[2];
    const float *pP[2], *pV[2];
#pragma unroll
    for (int it = 0; it < 2; it++) {
        int m = cm + it * 64;
        int w = (m << 4) + (((cc ^ ((m >> 1) & 3))) << 2);
        dP[it] = smem_u32(&sP[0][0]) + 4 * w;
        pP[it] = g_P + (size_t)(qbase + m) * S + cc * 4;
        int lin = tid + it * 256;
        int k = lin >> 5, c = lin & 31;
        dV[it] = smem_u32(&sV[0][0]) + 4 * vswz(k, c * 4);
        pV[it] = g_V + (size_t)(base + k) * DM + dc0 + c * 4;
    }

    float acc[4][4][4];
#pragma unroll
    for (int mi = 0; mi < 4; mi++)
#pragma unroll
        for (int ni = 0; ni < 4; ni++)
#pragma unroll
            for (int r = 0; r < 4; r++) acc[mi][ni][r] = 0.f;

    const int NT = (qt + 1) * 8;
#pragma unroll
    for (int t = 0; t < 2; t++) {
        const uint32_t off = t * 8192u;
        const int kc = t * 16;
#pragma unroll
        for (int it = 0; it < 2; it++) {
            cpa16(dP[it] + off, pP[it] + kc);
            cpa16(dV[it] + off, pV[it] + (size_t)kc * DM);
        }
        CP_COMMIT();
    }

    int cur = 0;
    for (int kt = 0; kt < NT; kt++) {
        CP_WAIT1();
        __syncthreads();
        {
            int nx = cur + 2; if (nx >= 3) nx -= 3;
            if (kt + 2 < NT) {
                const int kc = (kt + 2) * 16;
                const uint32_t off = nx * 8192u;
#pragma unroll
                for (int it = 0; it < 2; it++) {
                    cpa16(dP[it] + off, pP[it] + kc);
                    cpa16(dV[it] + off, pV[it] + (size_t)kc * DM);
                }
            }
            CP_COMMIT();
        }
        const uint32_t* cP = sP[cur];
        const uint32_t* cV = sV[cur];
#pragma unroll
        for (int ks = 0; ks < 2; ks++) {
            const int k0 = ks * 8;
            uint32_t a[4][4], b2[4][2];
#pragma unroll
            for (int mi = 0; mi < 4; mi++) {
                int row = wm + mi * 16 + lr;
                a[mi][0] = cP[swz(row,     k0 + lc)];
                a[mi][1] = cP[swz(row + 8, k0 + lc)];
                a[mi][2] = cP[swz(row,     k0 + lc + 4)];
                a[mi][3] = cP[swz(row + 8, k0 + lc + 4)];
            }
#pragma unroll
            for (int ni = 0; ni < 4; ni++) {
                int n = wn + ni * 8 + lr;
                b2[ni][0] = cV[vswz(k0 + lc,     n)];
                b2[ni][1] = cV[vswz(k0 + lc + 4, n)];
            }
#pragma unroll
            for (int mi = 0; mi < 4; mi++)
#pragma unroll
                for (int ni = 0; ni < 4; ni++)
                    mma_tf32(acc[mi][ni], a[mi], b2[ni]);
        }
        cur++; if (cur >= 3) cur = 0;
    }

#pragma unroll
    for (int mi = 0; mi < 4; mi++) {
#pragma unroll
        for (int h = 0; h < 2; h++) {
            int qrow = qt * 128 + wm + mi * 16 + lr + h * 8;
            float linv = 1.0f / g_L[base + qrow];
#pragma unroll
            for (int ni = 0; ni < 4; ni++) {
                int col = dc0 + wn + ni * 8 + 2 * lc;
                float2 o = {acc[mi][ni][h * 2 + 0] * linv,
                            acc[mi][ni][h * 2 + 1] * linv};
                *reinterpret_cast<float2*>(
                    &out[(size_t)(base + qrow) * DM + col]) = o;
            }
        }
    }
}

// ===========================================================================
extern "C" void kernel_launch(void* const* d_in, const int* in_sizes, int n_in,
                              void* d_out, int out_size)
{
    const float* X  = (const float*)d_in[0];
    const float* Wq = (const float*)d_in[1];
    const float* bq = (const float*)d_in[2];
    const float* Wk = (const float*)d_in[3];
    const float* bk = (const float*)d_in[4];
    const float* Wv = (const float*)d_in[5];
    const float* bv = (const float*)d_in[6];
    float* out = (float*)d_out;

    round_x_kernel<<<(size_t)ROWS * DM / 4 / 256, 256>>>(X);
    transpose_wv_kernel<<<dim3(32, 32), dim3(32, 8)>>>(Wv);
    prep_qk_kernel<<<dim3(32, 4), dim3(32, 8)>>>(Wq, bq, Wk, bk);
    gemm_tc_kernel<<<dim3(128, 1), 256>>>(nullptr, 1);      // Q|K projection
    gemm_tc_kernel<<<dim3(128, 8), 256>>>(bv, 0);           // V projection
    score_kernel<<<dim3(136, 8), 256>>>();                  // S = QK^T/8 (causal)
    rowexp_kernel<<<ROWS / 8, 256>>>();                     // softmax (in place)
    pv_kernel<<<dim3(S / 128, DM / 128, B), 256>>>(out);    // O = P V / l
}